// round 7
// baseline (speedup 1.0000x reference)
#include <cuda_runtime.h>
#include <cstdint>

// Problem dims
#define Bsz   64
#define Lseq  1024
#define Pdim  64
#define Hdim  256
#define OUTD  128

// Parallel decomposition: 16 clusters x 8 CTAs. Each cluster: 4 batch rows.
// Each CTA: 32 hidden units -> 96 gate rows (r,z,n blocks of 32).
#define CLUSTER  8
#define B_TILE   4
#define NTHREADS 384          // 96 rows * 4 batches, one output per thread
#define ROWS     96
#define UNITS    32
#define WH_PAD   260          // 256 + 4 pad (bank-conflict free)
#define WX_PAD   68           // 64 + 4 pad
#define HB_PAD   260

struct __align__(16) Smem {
    float Wx[ROWS * WX_PAD];        // encoder W_ih slice (96x64)
    float Wh[ROWS * WH_PAD];        // W_hh slice (96x256); reused for decoder weights
    float hb[2][B_TILE][HB_PAD];    // double-buffered full hidden state (4 batches x 256)
    float xb[B_TILE][WX_PAD];       // staged x_t
    float Asm[ROWS * B_TILE];       // input-gate partials
    float Gsm[ROWS * B_TILE];       // hidden-gate partials
    float giD[ROWS * B_TILE];       // decoder constant input gates
    float wa[Hdim];                 // attention hidden weight row
    float wdec[Hdim];               // decoder output weight
    float bA[ROWS];
    float bG[ROWS];
    float yb[Lseq * B_TILE];        // decoder outputs y[i][b]
    float red[64 * 6];              // final GEMM reduction scratch
};

__device__ __forceinline__ uint32_t s2u(const void* p) {
    uint32_t a;
    asm("{ .reg .u64 t; cvta.to.shared.u64 t, %1; cvt.u32.u64 %0, t; }"
        : "=r"(a) : "l"(p));
    return a;
}

__device__ __forceinline__ uint32_t mapa_r(uint32_t la, int r) {
    uint32_t ra;
    asm("mapa.shared::cluster.u32 %0, %1, %2;" : "=r"(ra) : "r"(la), "r"(r));
    return ra;
}

__device__ __forceinline__ void st_clu(uint32_t ra, float v) {
    asm volatile("st.shared::cluster.b32 [%0], %1;"
                 :: "r"(ra), "r"(__float_as_uint(v)) : "memory");
}

__device__ __forceinline__ void csync() {
    asm volatile("barrier.cluster.arrive.aligned;" ::: "memory");
    asm volatile("barrier.cluster.wait.aligned;" ::: "memory");
}

__device__ __forceinline__ float sigf(float v) { return 1.0f / (1.0f + expf(-v)); }

__device__ __forceinline__ float dot256(const float* __restrict__ Wr, const float* __restrict__ v) {
    const float4* w4 = (const float4*)Wr;
    const float4* v4 = (const float4*)v;
    float a0 = 0.f, a1 = 0.f;
#pragma unroll 8
    for (int k = 0; k < 64; k += 2) {
        float4 w = w4[k],     xx = v4[k];
        a0 = fmaf(w.x, xx.x, a0); a0 = fmaf(w.y, xx.y, a0);
        a0 = fmaf(w.z, xx.z, a0); a0 = fmaf(w.w, xx.w, a0);
        float4 w2 = w4[k + 1], x2 = v4[k + 1];
        a1 = fmaf(w2.x, x2.x, a1); a1 = fmaf(w2.y, x2.y, a1);
        a1 = fmaf(w2.z, x2.z, a1); a1 = fmaf(w2.w, x2.w, a1);
    }
    return a0 + a1;
}

__device__ __forceinline__ float dot64(const float* __restrict__ Wr, const float* __restrict__ v) {
    const float4* w4 = (const float4*)Wr;
    const float4* v4 = (const float4*)v;
    float a0 = 0.f, a1 = 0.f;
#pragma unroll
    for (int k = 0; k < 16; k += 2) {
        float4 w = w4[k],     xx = v4[k];
        a0 = fmaf(w.x, xx.x, a0); a0 = fmaf(w.y, xx.y, a0);
        a0 = fmaf(w.z, xx.z, a0); a0 = fmaf(w.w, xx.w, a0);
        float4 w2 = w4[k + 1], x2 = v4[k + 1];
        a1 = fmaf(w2.x, x2.x, a1); a1 = fmaf(w2.y, x2.y, a1);
        a1 = fmaf(w2.z, x2.z, a1); a1 = fmaf(w2.w, x2.w, a1);
    }
    return a0 + a1;
}

__global__ void __cluster_dims__(CLUSTER, 1, 1) __launch_bounds__(NTHREADS, 1)
attn_net_kernel(const float* __restrict__ x,
                const float* __restrict__ Wihe, const float* __restrict__ Whhe,
                const float* __restrict__ bihe, const float* __restrict__ bhhe,
                const float* __restrict__ Wihd, const float* __restrict__ Whhd,
                const float* __restrict__ bihd, const float* __restrict__ bhhd,
                const float* __restrict__ Wdec, const float* __restrict__ bdec_p,
                const float* __restrict__ Wattn, const float* __restrict__ battn,
                const float* __restrict__ Wout, const float* __restrict__ bout,
                float* __restrict__ out)
{
    extern __shared__ char smem_raw[];
    Smem& S = *reinterpret_cast<Smem*>(smem_raw);

    const int tid = threadIdx.x;
    uint32_t rank;
    asm("mov.u32 %0, %%cluster_ctarank;" : "=r"(rank));
    const int g   = blockIdx.x >> 3;        // cluster id 0..15
    const int b0  = g * B_TILE;             // batch base
    const int U0  = (int)rank * UNITS;      // hidden-unit base for this CTA
    const int row = tid >> 2;               // 0..95
    const int bb  = tid & 3;                // 0..3

    // ---------------- Phase 0: load weight slices ----------------
    for (int idx = tid; idx < ROWS * Pdim; idx += NTHREADS) {
        int lr = idx >> 6, k = idx & 63;
        int grow = (lr >> 5) * Hdim + U0 + (lr & 31);
        S.Wx[lr * WX_PAD + k] = Wihe[grow * Pdim + k];
    }
    for (int idx = tid; idx < ROWS * Hdim; idx += NTHREADS) {
        int lr = idx >> 8, k = idx & 255;
        int grow = (lr >> 5) * Hdim + U0 + (lr & 31);
        S.Wh[lr * WH_PAD + k] = Whhe[grow * Hdim + k];
    }
    for (int idx = tid; idx < ROWS; idx += NTHREADS) {
        int grow = (idx >> 5) * Hdim + U0 + (idx & 31);
        S.bA[idx] = bihe[grow];
        S.bG[idx] = bhhe[grow];
    }
    for (int idx = tid; idx < Hdim; idx += NTHREADS) {
        S.wa[idx]   = Wattn[Hdim + idx];   // W_attn[0, H + idx]
        S.wdec[idx] = Wdec[idx];           // W_dec_out[0, idx]
    }
    for (int idx = tid; idx < 2 * B_TILE * HB_PAD; idx += NTHREADS)
        ((float*)S.hb)[idx] = 0.f;
    __syncthreads();
    csync();

    // Precompute the 16 remote DSMEM addresses for the per-step h broadcast:
    // thread (u = tid>>2, b = tid&3) owns hb[buf][b][U0+u] in every peer CTA.
    uint32_t raddr[2][CLUSTER];
    if (tid < UNITS * B_TILE) {
        int u = tid >> 2, b = tid & 3;
#pragma unroll
        for (int buf = 0; buf < 2; buf++) {
            uint32_t la = s2u(&S.hb[buf][b][U0 + u]);
#pragma unroll
            for (int pr = 0; pr < CLUSTER; pr++)
                raddr[buf][pr] = mapa_r(la, pr);
        }
    }

    // Per-warp (warps 0-3 = batches 0-3) online-softmax state in registers.
    float m_run = -3.0e38f, Z_run = 0.f, C_run = 0.f;  // C_run: unit U0+lane

    // ---------------- Phase 1: encoder GRU + online softmax attention ----------------
    float rx = 0.f;
    if (tid < 256)
        rx = x[(b0 + (tid >> 6)) * (Lseq * Pdim) + (tid & 63)];

    for (int t = 0; t < Lseq; t++) {
        const int cur = t & 1, nxt = cur ^ 1;

        if (tid < 256) S.xb[tid >> 6][tid & 63] = rx;
        __syncthreads();
        if (tid < 256 && (t + 1) < Lseq)
            rx = x[(b0 + (tid >> 6)) * (Lseq * Pdim) + (t + 1) * Pdim + (tid & 63)];

        // gate GEMVs: every thread owns one (row, batch) output
        float a  = S.bA[row] + dot64 (&S.Wx[row * WX_PAD], S.xb[bb]);
        float gg = S.bG[row] + dot256(&S.Wh[row * WH_PAD], S.hb[cur][bb]);
        S.Asm[row * 4 + bb] = a;
        S.Gsm[row * 4 + bb] = gg;
        __syncthreads();

        // combine gates, push new hidden slice to all 8 CTAs
        if (tid < UNITS * B_TILE) {
            int u = tid >> 2, b = tid & 3;
            float r = sigf(S.Asm[u * 4 + b] + S.Gsm[u * 4 + b]);
            float z = sigf(S.Asm[(32 + u) * 4 + b] + S.Gsm[(32 + u) * 4 + b]);
            float n = tanhf(S.Asm[(64 + u) * 4 + b] + r * S.Gsm[(64 + u) * 4 + b]);
            float hn = (1.f - z) * n + z * S.hb[cur][b][U0 + u];
#pragma unroll
            for (int pr = 0; pr < CLUSTER; pr++) st_clu(raddr[nxt][pr], hn);
        }
        csync();

        // warp w owns batch w: h_proj + online-softmax + context, all in registers
        if (tid < 128) {
            int w = tid >> 5, l = tid & 31;
            float p = 0.f;
#pragma unroll
            for (int j = l; j < Hdim; j += 32) p += S.hb[nxt][w][j] * S.wa[j];
#pragma unroll
            for (int o = 16; o > 0; o >>= 1) p += __shfl_xor_sync(0xffffffffu, p, o);
            // p now replicated across lanes = h_proj[w] at step t
            float mn  = fmaxf(m_run, p);
            float sc  = expf(m_run - mn);
            float wgt = expf(p - mn);
            Z_run = Z_run * sc + wgt;
            m_run = mn;
            C_run = C_run * sc + wgt * S.hb[nxt][w][U0 + l];
        }
    }
    // last hidden state s0 lives in hb[0]

    // ---------------- Phase 1.5: context c, decoder constant gates ----------------
    // thread (warp w=batch, lane l=unit): write c[w][U0+l] into hb[1] of all CTAs
    if (tid < 128) {
        int w = tid >> 5, l = tid & 31;
        float cv = C_run / Z_run;
        uint32_t la = s2u(&S.hb[1][w][U0 + l]);
#pragma unroll
        for (int pr = 0; pr < CLUSTER; pr++) st_clu(mapa_r(la, pr), cv);
    }
    csync();

    // load decoder input weights into Wh region, compute giD = W_ih_d . c + b_ih_d
    for (int idx = tid; idx < ROWS * Hdim; idx += NTHREADS) {
        int lr = idx >> 8, k = idx & 255;
        int grow = (lr >> 5) * Hdim + U0 + (lr & 31);
        S.Wh[lr * WH_PAD + k] = Wihd[grow * Hdim + k];
    }
    for (int idx = tid; idx < ROWS; idx += NTHREADS) {
        int grow = (idx >> 5) * Hdim + U0 + (idx & 31);
        S.bA[idx] = bihd[grow];
        S.bG[idx] = bhhd[grow];
    }
    __syncthreads();
    S.giD[row * 4 + bb] = S.bA[row] + dot256(&S.Wh[row * WH_PAD], S.hb[1][bb]);
    __syncthreads();

    // load decoder recurrent weights
    for (int idx = tid; idx < ROWS * Hdim; idx += NTHREADS) {
        int lr = idx >> 8, k = idx & 255;
        int grow = (lr >> 5) * Hdim + U0 + (lr & 31);
        S.Wh[lr * WH_PAD + k] = Whhd[grow * Hdim + k];
    }
    const float bdec = bdec_p[0];
    __syncthreads();
    csync();

    // ---------------- Phase 2: decoder GRU (constant input gates) ----------------
    for (int i = 0; i < Lseq; i++) {
        const int cur = i & 1, nxt = cur ^ 1;

        float gg = S.bG[row] + dot256(&S.Wh[row * WH_PAD], S.hb[cur][bb]);
        S.Gsm[row * 4 + bb] = gg;
        __syncthreads();

        if (tid < 128) {
            int u = tid >> 2, b = tid & 3;
            float r = sigf(S.giD[u * 4 + b] + S.Gsm[u * 4 + b]);
            float z = sigf(S.giD[(32 + u) * 4 + b] + S.Gsm[(32 + u) * 4 + b]);
            float n = tanhf(S.giD[(64 + u) * 4 + b] + r * S.Gsm[(64 + u) * 4 + b]);
            float sn = (1.f - z) * n + z * S.hb[cur][b][U0 + u];
#pragma unroll
            for (int pr = 0; pr < CLUSTER; pr++) st_clu(raddr[nxt][pr], sn);
        }
        csync();

        // y_i[b] = sigmoid(s_new . w_dec + b_dec), warp w = batch w
        if (tid < 128) {
            int w = tid >> 5, l = tid & 31;
            float p = 0.f;
#pragma unroll
            for (int j = l; j < Hdim; j += 32) p += S.hb[nxt][w][j] * S.wdec[j];
#pragma unroll
            for (int o = 16; o > 0; o >>= 1) p += __shfl_xor_sync(0xffffffffu, p, o);
            if (l == 0) S.yb[i * 4 + w] = sigf(p + bdec);
        }
    }

    // ---------------- Phase 3: out = y @ W_out^T + b_out ----------------
    __syncthreads();
    {
        int part = tid / 64;            // 0..5, K-split
        int ob   = tid % 64;            // 16 o-rows x 4 batches
        int o    = (int)rank * 16 + (ob >> 2);
        int b    = ob & 3;
        float acc = 0.f;
        for (int i = part; i < Lseq; i += 6)
            acc += S.yb[i * 4 + b] * Wout[o * Lseq + i];
        S.red[ob * 6 + part] = acc;
    }
    __syncthreads();
    if (tid < 64) {
        int o = (int)rank * 16 + (tid >> 2);
        int b = tid & 3;
        float s = bout[o];
#pragma unroll
        for (int p6 = 0; p6 < 6; p6++) s += S.red[tid * 6 + p6];
        out[(b0 + b) * OUTD + o] = s;
    }
}

extern "C" void kernel_launch(void* const* d_in, const int* in_sizes, int n_in,
                              void* d_out, int out_size) {
    (void)in_sizes; (void)n_in; (void)out_size;
    cudaFuncSetAttribute(attn_net_kernel,
                         cudaFuncAttributeMaxDynamicSharedMemorySize,
                         (int)sizeof(Smem));
    attn_net_kernel<<<128, NTHREADS, sizeof(Smem)>>>(
        (const float*)d_in[0],  (const float*)d_in[1],  (const float*)d_in[2],
        (const float*)d_in[3],  (const float*)d_in[4],  (const float*)d_in[5],
        (const float*)d_in[6],  (const float*)d_in[7],  (const float*)d_in[8],
        (const float*)d_in[9],  (const float*)d_in[10], (const float*)d_in[11],
        (const float*)d_in[12], (const float*)d_in[13], (const float*)d_in[14],
        (float*)d_out);
}